// round 17
// baseline (speedup 1.0000x reference)
#include <cuda_runtime.h>
#include <math.h>
#include <stdint.h>

// Problem constants
#define T_STEPS 512
#define NBATCH  1024
#define IDIM    64
#define RDIM    256
#define NCTA    128
#define NTHR    512
#define NGRP    16

// ---------------- fragment-major activation buffers ----------------
// layout: [plane][bi][kt][mt][lane][4] u32   (plane0=bf16-hi pairs, plane1=lo)
// one (kt,mt) tile = 16 rows x 16 cols, matching mma.m16n8k16 A-fragments.
#define PS_H   (16*16*512)    // plane stride for h / m  (16 ktiles)
#define PS_CAT (16*32*512)    // plane stride for cat    (32 ktiles)
__device__ unsigned g_hF[2 * 16 * 16 * 4 * 32 * 4];
__device__ unsigned g_catF[2 * 16 * 32 * 4 * 32 * 4];
__device__ unsigned g_mF[2 * 16 * 16 * 4 * 32 * 4];
__device__ float    g_r1p[32 * NBATCH];        // regressor partials [bj*4+nt][n]
__device__ unsigned g_grp_bar[NGRP * 32];      // per-group barrier: cnt @+0, gen @+16

// ---------------- bf16 pack/split helpers ----------------
__device__ __forceinline__ unsigned packbf(float lo, float hi) {
    unsigned r;
    asm("cvt.rn.bf16x2.f32 %0, %1, %2;" : "=r"(r) : "f"(hi), "f"(lo));
    return r;
}
__device__ __forceinline__ float bflo2f(unsigned u) { return __uint_as_float(u << 16); }
__device__ __forceinline__ float bfhi2f(unsigned u) { return __uint_as_float(u & 0xffff0000u); }
__device__ __forceinline__ void split2(float f0, float f1, unsigned& hi, unsigned& lo) {
    hi = packbf(f0, f1);
    lo = packbf(f0 - bflo2f(hi), f1 - bfhi2f(hi));
}

// ---------------- mma / ldg helpers ----------------
__device__ __forceinline__ void mma_bf(float& d0, float& d1, float& d2, float& d3,
                                       const unsigned a[4], unsigned b0, unsigned b1) {
    asm("mma.sync.aligned.m16n8k16.row.col.f32.bf16.bf16.f32 "
        "{%0,%1,%2,%3},{%4,%5,%6,%7},{%8,%9},{%0,%1,%2,%3};"
        : "+f"(d0), "+f"(d1), "+f"(d2), "+f"(d3)
        : "r"(a[0]), "r"(a[1]), "r"(a[2]), "r"(a[3]), "r"(b0), "r"(b1));
}
__device__ __forceinline__ void ldg4cg(unsigned a[4], const unsigned* p) {
    asm("ld.global.cg.v4.u32 {%0,%1,%2,%3}, [%4];"
        : "=r"(a[0]), "=r"(a[1]), "=r"(a[2]), "=r"(a[3]) : "l"(p));
}

// ---------------- per-row-group barrier (8 CTAs) ----------------
__device__ __forceinline__ void group_barrier(int grp) {
    __threadfence();
    __syncthreads();
    if (threadIdx.x == 0) {
        unsigned* cnt = &g_grp_bar[grp * 32];
        unsigned* gen = &g_grp_bar[grp * 32 + 16];
        unsigned g = *((volatile unsigned*)gen);
        unsigned old = atomicAdd(cnt, 1u);
        if (old == 7) {
            *cnt = 0;
            __threadfence();
            *((volatile unsigned*)gen) = g + 1;
        } else {
            unsigned cur;
            do {
                asm volatile("ld.acquire.gpu.global.u32 %0, [%1];"
                             : "=r"(cur) : "l"(gen));
            } while (cur == g);
        }
    }
    __syncthreads();
}

// ---------------- split-bf16 GEMM over NKT ktiles ----------------
// Warp (mt, nt) computes a 16-row x 8-col tile. 3 mma per kt (6 with FUSE2).
// A-fragments double-buffered in registers (2-deep prefetch, MLP=4).
template<int NKT, bool FUSE2>
__device__ __forceinline__ void gemm_tc(
    const unsigned* __restrict__ Abase, int PS,
    const unsigned* __restrict__ W1, const unsigned* __restrict__ W2,
    float* Da, float* Dr, int mt, int nt, int lane)
{
    const unsigned* pa = Abase + mt * 128 + lane * 4;
    unsigned Ah[2][4], Al[2][4];
    ldg4cg(Ah[0], pa);
    ldg4cg(Al[0], pa + PS);
    #pragma unroll 4
    for (int kt = 0; kt < NKT; kt++) {
        const int cur = kt & 1, nxt = cur ^ 1;
        if (kt + 1 < NKT) {
            ldg4cg(Ah[nxt], pa + (kt + 1) * 512);
            ldg4cg(Al[nxt], pa + (kt + 1) * 512 + PS);
        }
        const unsigned* pb = W1 + ((kt * 8 + nt) * 32 + lane) * 2;       // hi plane
        const unsigned* pl = W1 + ((kt * 8 + 4 + nt) * 32 + lane) * 2;   // lo plane
        unsigned bh0 = pb[0], bh1 = pb[1], bl0 = pl[0], bl1 = pl[1];
        mma_bf(Da[0], Da[1], Da[2], Da[3], Ah[cur], bh0, bh1);
        mma_bf(Da[0], Da[1], Da[2], Da[3], Ah[cur], bl0, bl1);
        mma_bf(Da[0], Da[1], Da[2], Da[3], Al[cur], bh0, bh1);
        if (FUSE2) {
            const unsigned* qb = W2 + ((kt * 8 + nt) * 32 + lane) * 2;
            const unsigned* ql = W2 + ((kt * 8 + 4 + nt) * 32 + lane) * 2;
            unsigned ch0 = qb[0], ch1 = qb[1], cl0 = ql[0], cl1 = ql[1];
            mma_bf(Dr[0], Dr[1], Dr[2], Dr[3], Ah[cur], ch0, ch1);
            mma_bf(Dr[0], Dr[1], Dr[2], Dr[3], Ah[cur], cl0, cl1);
            mma_bf(Dr[0], Dr[1], Dr[2], Dr[3], Al[cur], ch0, ch1);
        }
    }
}

// tanh + hi/lo split + store this warp's uint2 half of the next-GEMM A-fragment.
// half=0 (nt even): elements {a0,a1}; half=1: {a2,a3}.
__device__ __forceinline__ void store_tanh_half(unsigned* dst, int PS,
                                                const float* D, int half) {
    unsigned H0, L0, H1, L1;
    split2(tanhf(D[0]), tanhf(D[1]), H0, L0);   // row gid
    split2(tanhf(D[2]), tanhf(D[3]), H1, L1);   // row gid+8
    *(uint2*)(dst + 2 * half)      = make_uint2(H0, H1);
    *(uint2*)(dst + PS + 2 * half) = make_uint2(L0, L1);
}

__global__ void __launch_bounds__(NTHR, 1)
recurrent_kernel(const float* __restrict__ inputs,
                 const float* __restrict__ Whp, const float* __restrict__ bhp,
                 const float* __restrict__ Wcp, const float* __restrict__ bcp,
                 const float* __restrict__ Wm,  const float* __restrict__ bm,
                 const float* __restrict__ Whpost, const float* __restrict__ bhpost,
                 const float* __restrict__ Wr1, const float* __restrict__ br1,
                 const float* __restrict__ Wr2, const float* __restrict__ br2,
                 float* __restrict__ out)
{
    extern __shared__ unsigned smemu[];
    unsigned* Whp_f    = smemu;             // 16kt * 512 = 8192
    unsigned* Wr1_f    = smemu + 8192;
    unsigned* Whpost_f = smemu + 16384;
    unsigned* Wm_f     = smemu + 24576;     // 32kt -> 16384
    unsigned* Wcp_f    = smemu + 40960;     // 4kt  -> 2048
    float*    bias_s   = (float*)(smemu + 43008);   // 192 floats

    const int tid  = threadIdx.x;
    const int wid  = tid >> 5;
    const int lane = tid & 31;
    const int gid  = lane >> 2;
    const int tig  = lane & 3;
    const int mt   = wid >> 2;     // m-tile 0..3 (16 rows each)
    const int nt   = wid & 3;      // n-tile 0..3 (8 cols each)
    const int half = nt & 1;       // which uint2 of the A-frag this warp stores
    const int cb   = nt * 8 + 2 * tig;   // local col base for bias / Wr2

    const int bi   = blockIdx.x >> 3;   // row group 0..15
    const int bj   = blockIdx.x & 7;    // col tile 0..7
    const int row0 = bi * 64;
    const int c0   = bj * 32;
    const int ktw  = bj * 2 + (nt >> 1);   // ktile this warp contributes to

    // ---- preprocess weights into B-fragment hi/lo planes in smem ----
    // dst[((kt*8 + plane*4 + nt)*32 + lane)*2 + reg]   (validated in R16)
    {
        const float* Ws[5]  = {Whp, Wr1, Whpost, Wm, Wcp};
        unsigned*    Wd[5]  = {Whp_f, Wr1_f, Whpost_f, Wm_f, Wcp_f};
        const int    KT[5]  = {16, 16, 16, 32, 4};
        for (int w = 0; w < 5; w++) {
            const float* W = Ws[w];
            unsigned* dst = Wd[w];
            int total = KT[w] * 512;
            for (int idx = tid; idx < total; idx += NTHR) {
                int reg = idx & 1, ln = (idx >> 1) & 31, nt2 = (idx >> 6) & 3;
                int plane = (idx >> 8) & 1, kt = idx >> 9;
                int g2 = ln >> 2, t2 = ln & 3;
                int n = c0 + nt2 * 8 + g2;
                int k = kt * 16 + reg * 8 + 2 * t2;
                float v0 = W[k * RDIM + n], v1 = W[(k + 1) * RDIM + n];
                unsigned hi = packbf(v0, v1);
                unsigned val = plane ? packbf(v0 - bflo2f(hi), v1 - bfhi2f(hi)) : hi;
                dst[((kt * 8 + plane * 4 + nt2) * 32 + ln) * 2 + reg] = val;
            }
        }
        if (tid < 32) {
            bias_s[tid]       = bhp[c0 + tid];
            bias_s[32 + tid]  = bcp[c0 + tid];
            bias_s[64 + tid]  = bm[c0 + tid];
            bias_s[96 + tid]  = bhpost[c0 + tid];
            bias_s[128 + tid] = br1[c0 + tid];
            bias_s[160 + tid] = Wr2[c0 + tid];
        }
    }
    const float br2v = __ldg(br2);
    __syncthreads();

    for (int t = 0; t < T_STEPS; t++) {
        // ================= Phase A =================
        // ---- S0: tcp = tanh(x @ Wcp + bcp) -> catF ktiles 16..31 ----
        {
            float Dx[4];
            Dx[0] = bias_s[32 + cb]; Dx[1] = bias_s[33 + cb];
            Dx[2] = Dx[0]; Dx[3] = Dx[1];
            const float* xg = inputs + (size_t)t * NBATCH * IDIM + (size_t)row0 * IDIM;
            #pragma unroll
            for (int kt = 0; kt < 4; kt++) {
                const float* p0 = xg + (mt * 16 + gid) * IDIM + kt * 16 + 2 * tig;
                float2 x00 = *(const float2*)p0;
                float2 x01 = *(const float2*)(p0 + 8);
                float2 x10 = *(const float2*)(p0 + 8 * IDIM);
                float2 x11 = *(const float2*)(p0 + 8 * IDIM + 8);
                unsigned Ah[4], Al[4];
                split2(x00.x, x00.y, Ah[0], Al[0]);
                split2(x10.x, x10.y, Ah[1], Al[1]);
                split2(x01.x, x01.y, Ah[2], Al[2]);
                split2(x11.x, x11.y, Ah[3], Al[3]);
                const unsigned* pb = Wcp_f + ((kt * 8 + nt) * 32 + lane) * 2;
                const unsigned* pl = Wcp_f + ((kt * 8 + 4 + nt) * 32 + lane) * 2;
                unsigned bh0 = pb[0], bh1 = pb[1], bl0 = pl[0], bl1 = pl[1];
                mma_bf(Dx[0], Dx[1], Dx[2], Dx[3], Ah, bh0, bh1);
                mma_bf(Dx[0], Dx[1], Dx[2], Dx[3], Ah, bl0, bl1);
                mma_bf(Dx[0], Dx[1], Dx[2], Dx[3], Al, bh0, bh1);
            }
            unsigned* dst = g_catF + (size_t)((bi * 32 + 16 + ktw) * 512 + mt * 128 + lane * 4);
            store_tanh_half(dst, PS_CAT, Dx, half);
        }

        if (t > 0) {
            // ---- S1 + S4: a = tanh(h@Whp+b); r1 = h@Wr1+b ----
            float Da[4], Dr[4];
            Da[0] = bias_s[cb];       Da[1] = bias_s[cb + 1];
            Da[2] = Da[0];            Da[3] = Da[1];
            Dr[0] = bias_s[128 + cb]; Dr[1] = bias_s[129 + cb];
            Dr[2] = Dr[0];            Dr[3] = Dr[1];
            gemm_tc<16, true>(g_hF + bi * 8192, PS_H, Whp_f, Wr1_f, Da, Dr, mt, nt, lane);
            unsigned* dst = g_catF + (size_t)((bi * 32 + ktw) * 512 + mt * 128 + lane * 4);
            store_tanh_half(dst, PS_CAT, Da, half);
            // S4 partials: v[row] = sum over this warp's 8 cols of relu(r)*Wr2
            float w0 = bias_s[160 + cb], w1 = bias_s[161 + cb];
            float vlo = fmaxf(Dr[0], 0.f) * w0 + fmaxf(Dr[1], 0.f) * w1;
            float vhi = fmaxf(Dr[2], 0.f) * w0 + fmaxf(Dr[3], 0.f) * w1;
            vlo += __shfl_xor_sync(0xffffffffu, vlo, 1);
            vlo += __shfl_xor_sync(0xffffffffu, vlo, 2);
            vhi += __shfl_xor_sync(0xffffffffu, vhi, 1);
            vhi += __shfl_xor_sync(0xffffffffu, vhi, 2);
            if (tig == 0) {
                int base = (bj * 4 + nt) * NBATCH + row0 + mt * 16 + gid;
                g_r1p[base]     = vlo;
                g_r1p[base + 8] = vhi;
            }
        } else {
            // h0 == 0 -> cat lo-tiles = tanh(bhp), uniform over rows
            float Da[4];
            Da[0] = bias_s[cb]; Da[1] = bias_s[cb + 1];
            Da[2] = Da[0];      Da[3] = Da[1];
            unsigned* dst = g_catF + (size_t)((bi * 32 + ktw) * 512 + mt * 128 + lane * 4);
            store_tanh_half(dst, PS_CAT, Da, half);
        }
        group_barrier(bi);

        // ================= Phase B: m = tanh(cat @ Wm + bm) =================
        if (bj == 0 && t > 0 && tid < 64) {
            int n = row0 + tid;
            float s = br2v;
            #pragma unroll
            for (int b = 0; b < 32; b++)
                s += __ldcg(&g_r1p[b * NBATCH + n]);
            out[(size_t)(t - 1) * NBATCH + n] = s;
        }
        {
            float Dm[4];
            Dm[0] = bias_s[64 + cb]; Dm[1] = bias_s[65 + cb];
            Dm[2] = Dm[0];           Dm[3] = Dm[1];
            gemm_tc<32, false>(g_catF + bi * 16384, PS_CAT, Wm_f, Wm_f, Dm, Dm, mt, nt, lane);
            unsigned* dst = g_mF + (size_t)((bi * 16 + ktw) * 512 + mt * 128 + lane * 4);
            store_tanh_half(dst, PS_H, Dm, half);
        }
        group_barrier(bi);

        // ================= Phase C: h = tanh(m @ Whpost + b) =================
        {
            float Dh[4];
            Dh[0] = bias_s[96 + cb]; Dh[1] = bias_s[97 + cb];
            Dh[2] = Dh[0];           Dh[3] = Dh[1];
            gemm_tc<16, false>(g_mF + bi * 8192, PS_H, Whpost_f, Whpost_f, Dh, Dh, mt, nt, lane);
            unsigned* dst = g_hF + (size_t)((bi * 16 + ktw) * 512 + mt * 128 + lane * 4);
            store_tanh_half(dst, PS_H, Dh, half);
        }
        group_barrier(bi);
    }

    // ================= Epilogue: regressor for final step =================
    {
        float Dr[4];
        Dr[0] = bias_s[128 + cb]; Dr[1] = bias_s[129 + cb];
        Dr[2] = Dr[0];            Dr[3] = Dr[1];
        gemm_tc<16, false>(g_hF + bi * 8192, PS_H, Wr1_f, Wr1_f, Dr, Dr, mt, nt, lane);
        float w0 = bias_s[160 + cb], w1 = bias_s[161 + cb];
        float vlo = fmaxf(Dr[0], 0.f) * w0 + fmaxf(Dr[1], 0.f) * w1;
        float vhi = fmaxf(Dr[2], 0.f) * w0 + fmaxf(Dr[3], 0.f) * w1;
        vlo += __shfl_xor_sync(0xffffffffu, vlo, 1);
        vlo += __shfl_xor_sync(0xffffffffu, vlo, 2);
        vhi += __shfl_xor_sync(0xffffffffu, vhi, 1);
        vhi += __shfl_xor_sync(0xffffffffu, vhi, 2);
        if (tig == 0) {
            int base = (bj * 4 + nt) * NBATCH + row0 + mt * 16 + gid;
            g_r1p[base]     = vlo;
            g_r1p[base + 8] = vhi;
        }
    }
    group_barrier(bi);
    if (bj == 0 && tid < 64) {
        int n = row0 + tid;
        float s = br2v;
        #pragma unroll
        for (int b = 0; b < 32; b++)
            s += __ldcg(&g_r1p[b * NBATCH + n]);
        out[(size_t)(T_STEPS - 1) * NBATCH + n] = s;
    }
}

extern "C" void kernel_launch(void* const* d_in, const int* in_sizes, int n_in,
                              void* d_out, int out_size)
{
    (void)in_sizes; (void)n_in; (void)out_size;
    const float* inputs = (const float*)d_in[0];
    const float* Whp    = (const float*)d_in[1];
    const float* bhp    = (const float*)d_in[2];
    const float* Wcp    = (const float*)d_in[3];
    const float* bcp    = (const float*)d_in[4];
    const float* Wm     = (const float*)d_in[5];
    const float* bm     = (const float*)d_in[6];
    const float* Whpost = (const float*)d_in[7];
    const float* bhpost = (const float*)d_in[8];
    const float* Wr1    = (const float*)d_in[9];
    const float* br1    = (const float*)d_in[10];
    const float* Wr2    = (const float*)d_in[11];
    const float* br2    = (const float*)d_in[12];
    float* out = (float*)d_out;

    // smem: fragment weights 43008 u32 + 192 floats bias = 172,800 B
    const size_t smem_bytes = (size_t)43200 * 4;
    cudaFuncSetAttribute(recurrent_kernel,
                         cudaFuncAttributeMaxDynamicSharedMemorySize,
                         (int)smem_bytes);

    recurrent_kernel<<<NCTA, NTHR, smem_bytes>>>(
        inputs, Whp, bhp, Wcp, bcp, Wm, bm, Whpost, bhpost,
        Wr1, br1, Wr2, br2, out);
}